// round 13
// baseline (speedup 1.0000x reference)
#include <cuda_runtime.h>
#include <cuda_fp16.h>
#include <cstdint>

#define DI 64
#define BR 128                  // rows per CTA (4 warps x 32 rows)
#define NTHR 128
#define STRD 72                 // halves per smem row
#define STG_BYTES 18432         // one stage: hi 64x72 + lo 64x72 halves
#define WH_B 36864              // weight region (A, then Wv)
#define BIAS_B 55296
#define SM_BYTES 55552
#define L2E 1.4426950408889634f

__device__ float g_bp[64];                        // log2e * (Wk^T bq)
__device__ __align__(16) __half g_nb[16 * 9216];  // per tile [hi|lo]; hi col64 = 1.0
__device__ __align__(16) __half g_wA[9216];       // A image (scaled by log2e)
__device__ __align__(16) __half g_wV[9216];       // Wv image

static __device__ __forceinline__ uint32_t smem_u32(const void* p) {
    uint32_t a;
    asm("{.reg .u64 t; cvta.to.shared.u64 t,%1; cvt.u32.u64 %0,t;}" : "=r"(a) : "l"(p));
    return a;
}
static __device__ __forceinline__ float ex2f(float x) {
    float y; asm("ex2.approx.f32 %0,%1;" : "=f"(y) : "f"(x)); return y;
}
#define LDSM4(r0,r1,r2,r3,a) asm volatile("ldmatrix.sync.aligned.m8n8.x4.shared.b16 {%0,%1,%2,%3},[%4];" \
    : "=r"(r0),"=r"(r1),"=r"(r2),"=r"(r3) : "r"(a))
#define LDSM4T(r0,r1,r2,r3,a) asm volatile("ldmatrix.sync.aligned.m8n8.x4.trans.shared.b16 {%0,%1,%2,%3},[%4];" \
    : "=r"(r0),"=r"(r1),"=r"(r2),"=r"(r3) : "r"(a))
#define LDSM2T(r0,r1,a) asm volatile("ldmatrix.sync.aligned.m8n8.x2.trans.shared.b16 {%0,%1},[%2];" \
    : "=r"(r0),"=r"(r1) : "r"(a))
#define MMA(d,a,b) asm volatile( \
    "mma.sync.aligned.m16n8k16.row.col.f32.f16.f16.f32 {%0,%1,%2,%3},{%4,%5,%6,%7},{%8,%9},{%0,%1,%2,%3};" \
    : "+f"((d)[0]),"+f"((d)[1]),"+f"((d)[2]),"+f"((d)[3]) \
    : "r"((a)[0]),"r"((a)[1]),"r"((a)[2]),"r"((a)[3]),"r"((b)[0]),"r"((b)[1]))
#define CPA16(dst, src)  asm volatile("cp.async.cg.shared.global [%0],[%1],16;" :: "r"(dst), "l"(src))
#define CPA_COMMIT()     asm volatile("cp.async.commit_group;" ::: "memory")
#define CPA_WAIT0()      asm volatile("cp.async.wait_group 0;" ::: "memory")

static __device__ __forceinline__ uint32_t h2pack(__half a, __half b) {
    return (uint32_t)__half_as_ushort(b) << 16 | (uint32_t)__half_as_ushort(a);
}
static __device__ __forceinline__ void split2(float x, float y, uint32_t& hi, uint32_t& lo) {
    __half hx = __float2half_rn(x), hy = __float2half_rn(y);
    __half lx = __float2half_rn(x - __half2float(hx));
    __half ly = __float2half_rn(y - __half2float(hy));
    hi = h2pack(hx, hy);
    lo = h2pack(lx, ly);
}
// one m16 half of a D-frag (8 n-blocks x 4) -> hi/lo A-frag slots [ks][4h..4h+3]
static __device__ __forceinline__ void d2a_half(const float D[8][4], float s0, float s1,
                                                uint32_t Ah[4][8], uint32_t Al[4][8], int h) {
    #pragma unroll
    for (int ks = 0; ks < 4; ++ks) {
        split2(D[2*ks][0]*s0,   D[2*ks][1]*s0,   Ah[ks][4*h+0], Al[ks][4*h+0]);
        split2(D[2*ks][2]*s1,   D[2*ks][3]*s1,   Ah[ks][4*h+1], Al[ks][4*h+1]);
        split2(D[2*ks+1][0]*s0, D[2*ks+1][1]*s0, Ah[ks][4*h+2], Al[ks][4*h+2]);
        split2(D[2*ks+1][2]*s1, D[2*ks+1][3]*s1, Ah[ks][4*h+3], Al[ks][4*h+3]);
    }
}
static __device__ __forceinline__ void d2a_half_hi(const float D[8][4], uint32_t Ah[4][8], int h) {
    #pragma unroll
    for (int ks = 0; ks < 4; ++ks) {
        Ah[ks][4*h+0] = h2pack(__float2half_rn(D[2*ks][0]),   __float2half_rn(D[2*ks][1]));
        Ah[ks][4*h+1] = h2pack(__float2half_rn(D[2*ks][2]),   __float2half_rn(D[2*ks][3]));
        Ah[ks][4*h+2] = h2pack(__float2half_rn(D[2*ks+1][0]), __float2half_rn(D[2*ks+1][1]));
        Ah[ks][4*h+3] = h2pack(__float2half_rn(D[2*ks+1][2]), __float2half_rn(D[2*ks+1][3]));
    }
}

// ONE prep kernel, grid 288 x 256
__global__ void prep(const float* __restrict__ Wq, const float* __restrict__ bq,
                     const float* __restrict__ Wk, const float* __restrict__ nb,
                     const float* __restrict__ Wv) {
    int b = blockIdx.x;
    if (b < 256) {
        int idx = b * 256 + threadIdx.x;
        int row = idx >> 6, d = idx & 63;
        int t = row >> 6, j = row & 63;
        float v = nb[idx];
        __half h = __float2half_rn(v);
        __half l = __float2half_rn(v - __half2float(h));
        g_nb[t*9216 + j*STRD + d] = h;
        g_nb[t*9216 + 4608 + j*STRD + d] = l;
        if (d == 63) g_nb[t*9216 + j*STRD + 64] = __float2half_rn(1.0f);  // ones col
    } else if (b < 272) {
        int idx = (b - 256) * 256 + threadIdx.x;
        int j = idx >> 6, d = idx & 63;
        float s = 0.f;
        #pragma unroll 8
        for (int t = 0; t < 64; ++t) s += Wk[t*64 + j] * Wq[t*64 + d];
        s *= L2E;
        __half h = __float2half_rn(s);
        __half l = __float2half_rn(s - __half2float(h));
        g_wA[j*STRD + d] = h;
        g_wA[4608 + j*STRD + d] = l;
        if (b == 256 && threadIdx.x < 64) {
            int jj = threadIdx.x;
            float bb = 0.f;
            #pragma unroll 8
            for (int t = 0; t < 64; ++t) bb += Wk[t*64 + jj] * bq[t];
            g_bp[jj] = bb * L2E;
        }
    } else {
        int idx = (b - 272) * 256 + threadIdx.x;
        int o = idx >> 6, e = idx & 63;
        float v = Wv[idx];
        __half h = __float2half_rn(v);
        __half l = __float2half_rn(v - __half2float(h));
        g_wV[o*STRD + e] = h;
        g_wV[4608 + o*STRD + e] = l;
    }
}

__global__ void __launch_bounds__(NTHR, 2)
gat_kernel(const float* __restrict__ x, const float* __restrict__ bv,
           float* __restrict__ out, int N) {
    extern __shared__ char sm[];
    const uint32_t su = smem_u32(sm);
    const int tid = threadIdx.x, lane = tid & 31, wid = tid >> 5;
    const int g = lane >> 2, tg = lane & 3;
    const int m0 = wid * 32;                 // 32 rows per warp
    const int n0 = blockIdx.x * BR;
    float* bias = (float*)(sm + BIAS_B);

    const int rN = ((lane >> 4) & 1) * 8 + (lane & 7);
    const int cN = ((lane >> 3) & 1) * 8;
    const int rT = ((lane >> 3) & 1) * 8 + (lane & 7);
    const int cT = ((lane >> 4) & 1) * 8;

    // ---- prologue: tile0 -> stage0, A image -> WH ----
    {
        const char* s0 = (const char*)g_nb;
        const char* sa = (const char*)g_wA;
        for (int i = tid; i < 1152; i += NTHR) {
            CPA16(su + i*16, s0 + i*16);
            CPA16(su + WH_B + i*16, sa + i*16);
        }
        CPA_COMMIT();
    }
    if (tid < 64) bias[tid] = g_bp[tid];

    // ---- x fragments (two m16 halves) straight from global ----
    uint32_t Xh[4][8], Xl[4][8];
    #pragma unroll
    for (int h = 0; h < 2; ++h) {
        int r0 = n0 + m0 + 16*h + g, r1 = r0 + 8;
        #pragma unroll
        for (int q = 0; q < 8; ++q) {
            int c = 2*tg + 8*q;
            float2 v0 = make_float2(0.f, 0.f), v1 = make_float2(0.f, 0.f);
            if (r0 < N) v0 = *(const float2*)&x[(size_t)r0*DI + c];
            if (r1 < N) v1 = *(const float2*)&x[(size_t)r1*DI + c];
            int ks = q >> 1;
            int sl = (q & 1) * 2;
            split2(v0.x, v0.y, Xh[ks][4*h + sl],     Xl[ks][4*h + sl]);
            split2(v1.x, v1.y, Xh[ks][4*h + sl + 1], Xl[ks][4*h + sl + 1]);
        }
    }
    CPA_WAIT0();
    __syncthreads();

    // ---- GEMM0: p = (x @ A^T + bp) * log2e  (3-pass) ----
    float D[2][8][4];
    #pragma unroll
    for (int h = 0; h < 2; ++h)
        #pragma unroll
        for (int b = 0; b < 8; ++b) {
            D[h][b][0] = bias[8*b + 2*tg]; D[h][b][1] = bias[8*b + 2*tg + 1];
            D[h][b][2] = D[h][b][0];       D[h][b][3] = D[h][b][1];
        }
    #pragma unroll
    for (int ks = 0; ks < 4; ++ks)
        #pragma unroll
        for (int P = 0; P < 4; ++P) {
            uint32_t off = ((16*P + rN)*STRD + 16*ks + cN) * 2;
            uint32_t bh[4], bl[4];
            LDSM4(bh[0], bh[1], bh[2], bh[3], su + WH_B + off);
            LDSM4(bl[0], bl[1], bl[2], bl[3], su + WH_B + 9216 + off);
            #pragma unroll
            for (int h = 0; h < 2; ++h) {
                MMA(D[h][2*P],   &Xh[ks][4*h], bh);   MMA(D[h][2*P],   &Xl[ks][4*h], bh);   MMA(D[h][2*P],   &Xh[ks][4*h], bl);
                MMA(D[h][2*P+1], &Xh[ks][4*h], bh+2); MMA(D[h][2*P+1], &Xl[ks][4*h], bh+2); MMA(D[h][2*P+1], &Xh[ks][4*h], bl+2);
            }
        }
    uint32_t Ph[4][8], Pl[4][8];
    d2a_half(D[0], 1.f, 1.f, Ph, Pl, 0);
    d2a_half(D[1], 1.f, 1.f, Ph, Pl, 1);

    // ---- flash loop state ----
    float ag[2][8][4];
    #pragma unroll
    for (int h = 0; h < 2; ++h)
        #pragma unroll
        for (int b = 0; b < 8; ++b)
            #pragma unroll
            for (int u = 0; u < 4; ++u) ag[h][b][u] = 0.f;
    float ags[2][4] = {{0.f,0.f,0.f,0.f},{0.f,0.f,0.f,0.f}};
    float mr[2][2] = {{-1e30f,-1e30f},{-1e30f,-1e30f}};
    uint32_t Th[4][8];

    for (int t = 0; t < 16; ++t) {
        CPA_WAIT0();
        __syncthreads();
        if (t + 1 < 16) {
            uint32_t dst = su + ((t + 1) & 1) * STG_BYTES;
            const char* src = (const char*)g_nb + (size_t)(t + 1) * STG_BYTES;
            for (int i = tid; i < 1152; i += NTHR) CPA16(dst + i*16, src + i*16);
        }
        if (t == 0) {   // Wv image into weight region freed by GEMM0
            const char* sv = (const char*)g_wV;
            for (int i = tid; i < 1152; i += NTHR) CPA16(su + WH_B + i*16, sv + i*16);
        }
        CPA_COMMIT();
        const uint32_t sH = su + (t & 1) * STG_BYTES, sL = sH + 9216;

        // GEMM1: S = p @ nb^T (3-pass), B-frags reused across both m-halves
        float S[2][8][4];
        #pragma unroll
        for (int h = 0; h < 2; ++h)
            #pragma unroll
            for (int b = 0; b < 8; ++b)
                #pragma unroll
                for (int v = 0; v < 4; ++v) S[h][b][v] = 0.f;
        #pragma unroll
        for (int ks = 0; ks < 4; ++ks)
            #pragma unroll
            for (int P = 0; P < 4; ++P) {
                uint32_t off = ((16*P + rN)*STRD + 16*ks + cN) * 2;
                uint32_t bh[4], bl[4];
                LDSM4(bh[0], bh[1], bh[2], bh[3], sH + off);
                LDSM4(bl[0], bl[1], bl[2], bl[3], sL + off);
                #pragma unroll
                for (int h = 0; h < 2; ++h) {
                    MMA(S[h][2*P],   &Ph[ks][4*h], bh);   MMA(S[h][2*P],   &Pl[ks][4*h], bh);   MMA(S[h][2*P],   &Ph[ks][4*h], bl);
                    MMA(S[h][2*P+1], &Ph[ks][4*h], bh+2); MMA(S[h][2*P+1], &Pl[ks][4*h], bh+2); MMA(S[h][2*P+1], &Ph[ks][4*h], bl+2);
                }
            }

        // online softmax (log2 domain) per half
        #pragma unroll
        for (int h = 0; h < 2; ++h) {
            float mx0 = -1e30f, mx1 = -1e30f;
            #pragma unroll
            for (int b = 0; b < 8; ++b) {
                mx0 = fmaxf(mx0, fmaxf(S[h][b][0], S[h][b][1]));
                mx1 = fmaxf(mx1, fmaxf(S[h][b][2], S[h][b][3]));
            }
            mx0 = fmaxf(mx0, __shfl_xor_sync(0xFFFFFFFFu, mx0, 1));
            mx0 = fmaxf(mx0, __shfl_xor_sync(0xFFFFFFFFu, mx0, 2));
            mx1 = fmaxf(mx1, __shfl_xor_sync(0xFFFFFFFFu, mx1, 1));
            mx1 = fmaxf(mx1, __shfl_xor_sync(0xFFFFFFFFu, mx1, 2));
            float mn0 = fmaxf(mr[h][0], mx0), mn1 = fmaxf(mr[h][1], mx1);
            float sc0 = ex2f(mr[h][0] - mn0), sc1 = ex2f(mr[h][1] - mn1);
            mr[h][0] = mn0; mr[h][1] = mn1;
            #pragma unroll
            for (int b = 0; b < 8; ++b) {
                S[h][b][0] = ex2f(S[h][b][0] - mn0);
                S[h][b][1] = ex2f(S[h][b][1] - mn0);
                S[h][b][2] = ex2f(S[h][b][2] - mn1);
                S[h][b][3] = ex2f(S[h][b][3] - mn1);
            }
            d2a_half_hi(S[h], Th, h);
            #pragma unroll
            for (int b = 0; b < 8; ++b) {
                ag[h][b][0] *= sc0; ag[h][b][1] *= sc0;
                ag[h][b][2] *= sc1; ag[h][b][3] *= sc1;
            }
            ags[h][0] *= sc0; ags[h][2] *= sc1;
        }

        // GEMM2: ag += attn @ nb (hi-only), B-frags reused across halves; ones col -> row sums
        #pragma unroll
        for (int ks = 0; ks < 4; ++ks) {
            #pragma unroll
            for (int P = 0; P < 4; ++P) {
                uint32_t off = ((16*ks + rT)*STRD + 16*P + cT) * 2;
                uint32_t bh[4];
                LDSM4T(bh[0], bh[1], bh[2], bh[3], sH + off);
                #pragma unroll
                for (int h = 0; h < 2; ++h) {
                    MMA(ag[h][2*P],   &Th[ks][4*h], bh);
                    MMA(ag[h][2*P+1], &Th[ks][4*h], bh+2);
                }
            }
            uint32_t b0, b1;
            LDSM2T(b0, b1, sH + ((16*ks + rT)*STRD + 64) * 2);
            uint32_t bs[2] = {b0, b1};
            #pragma unroll
            for (int h = 0; h < 2; ++h) MMA(ags[h], &Th[ks][4*h], bs);
        }
    }

    // ---- row sums from ones column (col 64 -> lanes tg==0): broadcast within quad ----
    float lr00 = __shfl_sync(0xFFFFFFFFu, ags[0][0], lane & ~3);
    float lr01 = __shfl_sync(0xFFFFFFFFu, ags[0][2], lane & ~3);
    float lr10 = __shfl_sync(0xFFFFFFFFu, ags[1][0], lane & ~3);
    float lr11 = __shfl_sync(0xFFFFFFFFu, ags[1][2], lane & ~3);

    CPA_WAIT0();                 // Wv image landed long ago
    if (tid < 64) bias[tid] = bv[tid];
    __syncthreads();

    // ---- epilogue: normalize -> A-frags; GEMM3 (3-pass, Wv in WH); store ----
    uint32_t Gh[4][8], Gl[4][8];
    d2a_half(ag[0], 1.0f/lr00, 1.0f/lr01, Gh, Gl, 0);
    d2a_half(ag[1], 1.0f/lr10, 1.0f/lr11, Gh, Gl, 1);
    float O[2][8][4];
    #pragma unroll
    for (int h = 0; h < 2; ++h)
        #pragma unroll
        for (int b = 0; b < 8; ++b) {
            O[h][b][0] = bias[8*b + 2*tg]; O[h][b][1] = bias[8*b + 2*tg + 1];
            O[h][b][2] = O[h][b][0];       O[h][b][3] = O[h][b][1];
        }
    #pragma unroll
    for (int ks = 0; ks < 4; ++ks)
        #pragma unroll
        for (int P = 0; P < 4; ++P) {
            uint32_t off = ((16*P + rN)*STRD + 16*ks + cN) * 2;
            uint32_t bh[4], bl[4];
            LDSM4(bh[0], bh[1], bh[2], bh[3], su + WH_B + off);
            LDSM4(bl[0], bl[1], bl[2], bl[3], su + WH_B + 9216 + off);
            #pragma unroll
            for (int h = 0; h < 2; ++h) {
                MMA(O[h][2*P],   &Gh[ks][4*h], bh);   MMA(O[h][2*P],   &Gl[ks][4*h], bh);   MMA(O[h][2*P],   &Gh[ks][4*h], bl);
                MMA(O[h][2*P+1], &Gh[ks][4*h], bh+2); MMA(O[h][2*P+1], &Gl[ks][4*h], bh+2); MMA(O[h][2*P+1], &Gh[ks][4*h], bl+2);
            }
        }
    #pragma unroll
    for (int h = 0; h < 2; ++h)
        #pragma unroll
        for (int b = 0; b < 8; ++b) {
            int col = 8*b + 2*tg;
            int row0 = n0 + m0 + 16*h + g;
            if (row0 < N) *(float2*)&out[(size_t)row0*DI + col] = make_float2(O[h][b][0], O[h][b][1]);
            int row1 = row0 + 8;
            if (row1 < N) *(float2*)&out[(size_t)row1*DI + col] = make_float2(O[h][b][2], O[h][b][3]);
        }
}

extern "C" void kernel_launch(void* const* d_in, const int* in_sizes, int n_in,
                              void* d_out, int out_size) {
    const float* x  = (const float*)d_in[0];
    const float* nb = (const float*)d_in[1];
    const float* Wq = (const float*)d_in[2];
    const float* bq = (const float*)d_in[3];
    const float* Wk = (const float*)d_in[4];
    // d_in[5] = bk drops out of softmax
    const float* Wv = (const float*)d_in[6];
    const float* bv = (const float*)d_in[7];
    float* out = (float*)d_out;
    const int N = in_sizes[0] / DI;
    cudaFuncSetAttribute(gat_kernel, cudaFuncAttributeMaxDynamicSharedMemorySize, SM_BYTES);
    prep<<<288, 256>>>(Wq, bq, Wk, nb, Wv);
    gat_kernel<<<(N + BR - 1) / BR, NTHR, SM_BYTES>>>(x, bv, out, N);
}

// round 14
// speedup vs baseline: 1.1406x; 1.1406x over previous
#include <cuda_runtime.h>
#include <cuda_fp16.h>
#include <cstdint>

#define DI 64
#define BR 64
#define NTHR 128
#define STRD 72                 // halves per smem row
#define STG_BYTES 18432         // one stage: hi 64x72 + lo 64x72 halves
#define WH_B 36864              // weight region (A, then Wv)
#define BIAS_B 55296
#define SM_BYTES 55552
#define L2E 1.4426950408889634f

__device__ float g_bp[64];                        // log2e * (Wk^T bq)
__device__ __align__(16) __half g_nb[16 * 9216];  // per tile [hi|lo]; hi col64 = 1.0
__device__ __align__(16) __half g_wA[9216];       // A image (scaled by log2e)
__device__ __align__(16) __half g_wV[9216];       // Wv image

static __device__ __forceinline__ uint32_t smem_u32(const void* p) {
    uint32_t a;
    asm("{.reg .u64 t; cvta.to.shared.u64 t,%1; cvt.u32.u64 %0,t;}" : "=r"(a) : "l"(p));
    return a;
}
static __device__ __forceinline__ float ex2f(float x) {
    float y; asm("ex2.approx.f32 %0,%1;" : "=f"(y) : "f"(x)); return y;
}
#define LDSM4(r0,r1,r2,r3,a) asm volatile("ldmatrix.sync.aligned.m8n8.x4.shared.b16 {%0,%1,%2,%3},[%4];" \
    : "=r"(r0),"=r"(r1),"=r"(r2),"=r"(r3) : "r"(a))
#define LDSM4T(r0,r1,r2,r3,a) asm volatile("ldmatrix.sync.aligned.m8n8.x4.trans.shared.b16 {%0,%1,%2,%3},[%4];" \
    : "=r"(r0),"=r"(r1),"=r"(r2),"=r"(r3) : "r"(a))
#define LDSM2T(r0,r1,a) asm volatile("ldmatrix.sync.aligned.m8n8.x2.trans.shared.b16 {%0,%1},[%2];" \
    : "=r"(r0),"=r"(r1) : "r"(a))
#define MMA(d,a,b) asm volatile( \
    "mma.sync.aligned.m16n8k16.row.col.f32.f16.f16.f32 {%0,%1,%2,%3},{%4,%5,%6,%7},{%8,%9},{%0,%1,%2,%3};" \
    : "+f"((d)[0]),"+f"((d)[1]),"+f"((d)[2]),"+f"((d)[3]) \
    : "r"((a)[0]),"r"((a)[1]),"r"((a)[2]),"r"((a)[3]),"r"((b)[0]),"r"((b)[1]))
#define CPA16(dst, src)  asm volatile("cp.async.cg.shared.global [%0],[%1],16;" :: "r"(dst), "l"(src))
#define CPA_COMMIT()     asm volatile("cp.async.commit_group;" ::: "memory")
#define CPA_WAIT0()      asm volatile("cp.async.wait_group 0;" ::: "memory")

static __device__ __forceinline__ uint32_t h2pack(__half a, __half b) {
    return (uint32_t)__half_as_ushort(b) << 16 | (uint32_t)__half_as_ushort(a);
}
static __device__ __forceinline__ void split2(float x, float y, uint32_t& hi, uint32_t& lo) {
    __half hx = __float2half_rn(x), hy = __float2half_rn(y);
    __half lx = __float2half_rn(x - __half2float(hx));
    __half ly = __float2half_rn(y - __half2float(hy));
    hi = h2pack(hx, hy);
    lo = h2pack(lx, ly);
}
static __device__ __forceinline__ void dfrag_to_afrag(const float D[8][4], float s0, float s1,
                                                      uint32_t Ah[4][4], uint32_t Al[4][4]) {
    #pragma unroll
    for (int ks = 0; ks < 4; ++ks) {
        split2(D[2*ks][0]*s0,   D[2*ks][1]*s0,   Ah[ks][0], Al[ks][0]);
        split2(D[2*ks][2]*s1,   D[2*ks][3]*s1,   Ah[ks][1], Al[ks][1]);
        split2(D[2*ks+1][0]*s0, D[2*ks+1][1]*s0, Ah[ks][2], Al[ks][2]);
        split2(D[2*ks+1][2]*s1, D[2*ks+1][3]*s1, Ah[ks][3], Al[ks][3]);
    }
}

// ONE prep kernel, grid 288 x 256
__global__ void prep(const float* __restrict__ Wq, const float* __restrict__ bq,
                     const float* __restrict__ Wk, const float* __restrict__ nb,
                     const float* __restrict__ Wv) {
    int b = blockIdx.x;
    if (b < 256) {
        int idx = b * 256 + threadIdx.x;
        int row = idx >> 6, d = idx & 63;
        int t = row >> 6, j = row & 63;
        float v = nb[idx];
        __half h = __float2half_rn(v);
        __half l = __float2half_rn(v - __half2float(h));
        g_nb[t*9216 + j*STRD + d] = h;
        g_nb[t*9216 + 4608 + j*STRD + d] = l;
        if (d == 63) g_nb[t*9216 + j*STRD + 64] = __float2half_rn(1.0f);  // ones col
    } else if (b < 272) {
        int idx = (b - 256) * 256 + threadIdx.x;
        int j = idx >> 6, d = idx & 63;
        float s = 0.f;
        #pragma unroll 8
        for (int t = 0; t < 64; ++t) s += Wk[t*64 + j] * Wq[t*64 + d];
        s *= L2E;
        __half h = __float2half_rn(s);
        __half l = __float2half_rn(s - __half2float(h));
        g_wA[j*STRD + d] = h;
        g_wA[4608 + j*STRD + d] = l;
        if (b == 256 && threadIdx.x < 64) {
            int jj = threadIdx.x;
            float bb = 0.f;
            #pragma unroll 8
            for (int t = 0; t < 64; ++t) bb += Wk[t*64 + jj] * bq[t];
            g_bp[jj] = bb * L2E;
        }
    } else {
        int idx = (b - 272) * 256 + threadIdx.x;
        int o = idx >> 6, e = idx & 63;
        float v = Wv[idx];
        __half h = __float2half_rn(v);
        __half l = __float2half_rn(v - __half2float(h));
        g_wV[o*STRD + e] = h;
        g_wV[4608 + o*STRD + e] = l;
    }
}

__global__ void __launch_bounds__(NTHR, 4)
gat_kernel(const float* __restrict__ x, const float* __restrict__ bv,
           float* __restrict__ out, int N) {
    extern __shared__ char sm[];
    const uint32_t su = smem_u32(sm);
    const int tid = threadIdx.x, lane = tid & 31, wid = tid >> 5;
    const int g = lane >> 2, tg = lane & 3;
    const int m0 = wid * 16;
    const int n0 = blockIdx.x * BR;
    float* bias = (float*)(sm + BIAS_B);

    const int rN = ((lane >> 4) & 1) * 8 + (lane & 7);
    const int cN = ((lane >> 3) & 1) * 8;
    const int rT = ((lane >> 3) & 1) * 8 + (lane & 7);
    const int cT = ((lane >> 4) & 1) * 8;

    // ---- prologue: tile0 -> stage0, A image -> WH ----
    {
        const char* s0 = (const char*)g_nb;
        const char* sa = (const char*)g_wA;
        for (int i = tid; i < 1152; i += NTHR) {
            CPA16(su + i*16, s0 + i*16);
            CPA16(su + WH_B + i*16, sa + i*16);
        }
        CPA_COMMIT();
    }
    if (tid < 64) bias[tid] = g_bp[tid];

    // ---- x fragments straight from global ----
    uint32_t Xh[4][4], Xl[4][4];
    {
        int r0 = n0 + m0 + g, r1 = r0 + 8;
        #pragma unroll
        for (int q = 0; q < 8; ++q) {
            int c = 2*tg + 8*q;
            float2 v0 = make_float2(0.f, 0.f), v1 = make_float2(0.f, 0.f);
            if (r0 < N) v0 = *(const float2*)&x[(size_t)r0*DI + c];
            if (r1 < N) v1 = *(const float2*)&x[(size_t)r1*DI + c];
            int ks = q >> 1;
            if ((q & 1) == 0) {
                split2(v0.x, v0.y, Xh[ks][0], Xl[ks][0]);
                split2(v1.x, v1.y, Xh[ks][1], Xl[ks][1]);
            } else {
                split2(v0.x, v0.y, Xh[ks][2], Xl[ks][2]);
                split2(v1.x, v1.y, Xh[ks][3], Xl[ks][3]);
            }
        }
    }
    CPA_WAIT0();
    __syncthreads();

    // ---- GEMM0: p = (x @ A^T + bp) * log2e  (3-pass, precision-critical) ----
    float D[8][4];
    #pragma unroll
    for (int b = 0; b < 8; ++b) {
        D[b][0] = bias[8*b + 2*tg]; D[b][1] = bias[8*b + 2*tg + 1];
        D[b][2] = D[b][0];          D[b][3] = D[b][1];
    }
    #pragma unroll
    for (int ks = 0; ks < 4; ++ks)
        #pragma unroll
        for (int P = 0; P < 4; ++P) {
            uint32_t off = ((16*P + rN)*STRD + 16*ks + cN) * 2;
            uint32_t bh[4], bl[4];
            LDSM4(bh[0], bh[1], bh[2], bh[3], su + WH_B + off);
            LDSM4(bl[0], bl[1], bl[2], bl[3], su + WH_B + 9216 + off);
            MMA(D[2*P],   Xh[ks], bh);     MMA(D[2*P],   Xl[ks], bh);     MMA(D[2*P],   Xh[ks], bl);
            MMA(D[2*P+1], Xh[ks], bh+2);   MMA(D[2*P+1], Xl[ks], bh+2);   MMA(D[2*P+1], Xh[ks], bl+2);
        }
    uint32_t Ph[4][4], Pl[4][4];
    dfrag_to_afrag(D, 1.f, 1.f, Ph, Pl);

    // ---- flash loop (double-buffered nb stages) ----
    float ag[8][4];
    #pragma unroll
    for (int b = 0; b < 8; ++b)
        #pragma unroll
        for (int u = 0; u < 4; ++u) ag[b][u] = 0.f;
    float ags[4] = {0.f, 0.f, 0.f, 0.f};   // ones-column accumulator (row sums)
    float mr0 = -1e30f, mr1 = -1e30f;

    for (int t = 0; t < 16; ++t) {
        CPA_WAIT0();
        __syncthreads();
        {
            int nxt = t + 1;
            uint32_t dst = su + (nxt & 1) * STG_BYTES;
            if (nxt < 16) {
                const char* src = (const char*)g_nb + (size_t)nxt * STG_BYTES;
                for (int i = tid; i < 1152; i += NTHR) CPA16(dst + i*16, src + i*16);
            }
        }
        if (t == 0) {   // Wv image into weight region freed by GEMM0
            const char* sv = (const char*)g_wV;
            for (int i = tid; i < 1152; i += NTHR) CPA16(su + WH_B + i*16, sv + i*16);
        }
        CPA_COMMIT();
        const uint32_t sH = su + (t & 1) * STG_BYTES, sL = sH + 9216;

        // GEMM1: S = p @ nb^T (3-pass: logit precision drives softmax)
        float S[8][4];
        #pragma unroll
        for (int b = 0; b < 8; ++b)
            #pragma unroll
            for (int u = 0; u < 4; ++u) S[b][u] = 0.f;
        #pragma unroll
        for (int ks = 0; ks < 4; ++ks)
            #pragma unroll
            for (int P = 0; P < 4; ++P) {
                uint32_t off = ((16*P + rN)*STRD + 16*ks + cN) * 2;
                uint32_t bh[4], bl[4];
                LDSM4(bh[0], bh[1], bh[2], bh[3], sH + off);
                LDSM4(bl[0], bl[1], bl[2], bl[3], sL + off);
                MMA(S[2*P],   Ph[ks], bh);   MMA(S[2*P],   Pl[ks], bh);   MMA(S[2*P],   Ph[ks], bl);
                MMA(S[2*P+1], Ph[ks], bh+2); MMA(S[2*P+1], Pl[ks], bh+2); MMA(S[2*P+1], Ph[ks], bl+2);
            }

        // online softmax (log2 domain): f32 max + delta, then fused cvt.f16x2 + ex2.f16x2 -> Th
        float mx0 = -1e30f, mx1 = -1e30f;
        #pragma unroll
        for (int b = 0; b < 8; ++b) {
            mx0 = fmaxf(mx0, fmaxf(S[b][0], S[b][1]));
            mx1 = fmaxf(mx1, fmaxf(S[b][2], S[b][3]));
        }
        mx0 = fmaxf(mx0, __shfl_xor_sync(0xFFFFFFFFu, mx0, 1));
        mx0 = fmaxf(mx0, __shfl_xor_sync(0xFFFFFFFFu, mx0, 2));
        mx1 = fmaxf(mx1, __shfl_xor_sync(0xFFFFFFFFu, mx1, 1));
        mx1 = fmaxf(mx1, __shfl_xor_sync(0xFFFFFFFFu, mx1, 2));
        float mn0 = fmaxf(mr0, mx0), mn1 = fmaxf(mr1, mx1);
        float sc0 = ex2f(mr0 - mn0), sc1 = ex2f(mr1 - mn1);
        mr0 = mn0; mr1 = mn1;

        uint32_t Th[4][4];
        #pragma unroll
        for (int b = 0; b < 8; ++b) {
            int ks = b >> 1, sl = (b & 1) * 2;
            uint32_t p0, p1;
            asm("cvt.rn.f16x2.f32 %0,%1,%2;" : "=r"(p0) : "f"(S[b][1]-mn0), "f"(S[b][0]-mn0));
            asm("cvt.rn.f16x2.f32 %0,%1,%2;" : "=r"(p1) : "f"(S[b][3]-mn1), "f"(S[b][2]-mn1));
            asm("ex2.approx.f16x2 %0,%1;" : "=r"(Th[ks][sl])     : "r"(p0));
            asm("ex2.approx.f16x2 %0,%1;" : "=r"(Th[ks][sl + 1]) : "r"(p1));
        }

        #pragma unroll
        for (int b = 0; b < 8; ++b) {
            ag[b][0] *= sc0; ag[b][1] *= sc0;
            ag[b][2] *= sc1; ag[b][3] *= sc1;
        }
        ags[0] *= sc0; ags[2] *= sc1;

        // GEMM2: ag += attn @ nb (single pass); ones column -> row sums
        #pragma unroll
        for (int ks = 0; ks < 4; ++ks) {
            #pragma unroll
            for (int P = 0; P < 4; ++P) {
                uint32_t off = ((16*ks + rT)*STRD + 16*P + cT) * 2;
                uint32_t bh[4];
                LDSM4T(bh[0], bh[1], bh[2], bh[3], sH + off);
                MMA(ag[2*P],   Th[ks], bh);
                MMA(ag[2*P+1], Th[ks], bh+2);
            }
            uint32_t b0, b1;
            LDSM2T(b0, b1, sH + ((16*ks + rT)*STRD + 64) * 2);
            uint32_t bs[2] = {b0, b1};
            MMA(ags, Th[ks], bs);
        }
    }

    // ---- row sums from ones column (lanes tg==0): broadcast within quad ----
    float lr0 = __shfl_sync(0xFFFFFFFFu, ags[0], lane & ~3);
    float lr1 = __shfl_sync(0xFFFFFFFFu, ags[2], lane & ~3);

    CPA_WAIT0();                 // Wv image landed long ago
    if (tid < 64) bias[tid] = bv[tid];
    __syncthreads();

    // ---- epilogue: normalize -> A-frags; GEMM3 (3-pass, Wv in WH); store ----
    float inv0 = 1.0f / lr0, inv1 = 1.0f / lr1;
    uint32_t Gh[4][4], Gl[4][4];
    dfrag_to_afrag(ag, inv0, inv1, Gh, Gl);
    float O[8][4];
    #pragma unroll
    for (int b = 0; b < 8; ++b) {
        O[b][0] = bias[8*b + 2*tg]; O[b][1] = bias[8*b + 2*tg + 1];
        O[b][2] = O[b][0];          O[b][3] = O[b][1];
    }
    #pragma unroll
    for (int ks = 0; ks < 4; ++ks)
        #pragma unroll
        for (int P = 0; P < 4; ++P) {
            uint32_t off = ((16*P + rN)*STRD + 16*ks + cN) * 2;
            uint32_t bh[4], bl[4];
            LDSM4(bh[0], bh[1], bh[2], bh[3], su + WH_B + off);
            LDSM4(bl[0], bl[1], bl[2], bl[3], su + WH_B + 9216 + off);
            MMA(O[2*P],   Gh[ks], bh);   MMA(O[2*P],   Gl[ks], bh);   MMA(O[2*P],   Gh[ks], bl);
            MMA(O[2*P+1], Gh[ks], bh+2); MMA(O[2*P+1], Gl[ks], bh+2); MMA(O[2*P+1], Gh[ks], bl+2);
        }
    #pragma unroll
    for (int b = 0; b < 8; ++b) {
        int col = 8*b + 2*tg;
        int row0 = n0 + m0 + g;
        if (row0 < N) *(float2*)&out[(size_t)row0*DI + col] = make_float2(O[b][0], O[b][1]);
        int row1 = row0 + 8;
        if (row1 < N) *(float2*)&out[(size_t)row1*DI + col] = make_float2(O[b][2], O[b][3]);
    }
}

extern "C" void kernel_launch(void* const* d_in, const int* in_sizes, int n_in,
                              void* d_out, int out_size) {
    const float* x  = (const float*)d_in[0];
    const float* nb = (const float*)d_in[1];
    const float* Wq = (const float*)d_in[2];
    const float* bq = (const float*)d_in[3];
    const float* Wk = (const float*)d_in[4];
    // d_in[5] = bk drops out of softmax
    const float* Wv = (const float*)d_in[6];
    const float* bv = (const float*)d_in[7];
    float* out = (float*)d_out;
    const int N = in_sizes[0] / DI;
    cudaFuncSetAttribute(gat_kernel, cudaFuncAttributeMaxDynamicSharedMemorySize, SM_BYTES);
    prep<<<288, 256>>>(Wq, bq, Wk, nb, Wv);
    gat_kernel<<<(N + BR - 1) / BR, NTHR, SM_BYTES>>>(x, bv, out, N);
}

// round 15
// speedup vs baseline: 1.1764x; 1.0314x over previous
#include <cuda_runtime.h>
#include <cuda_fp16.h>
#include <cstdint>

#define DI 64
#define BR 64
#define NTHR 128
#define STRD 72                 // halves per smem row
#define STG_BYTES 18432         // one stage: hi 64x72 + lo 64x72 halves
#define WH_B 36864              // weight region (A, then Wv)
#define BIAS_B 55296
#define SM_BYTES 55552
#define L2E 1.4426950408889634f

__device__ float g_bp[64];                        // log2e * (Wk^T bq)
__device__ __align__(16) __half g_nb[16 * 9216];  // per tile [hi|lo]; hi col64 = 1.0
__device__ __align__(16) __half g_wA[9216];       // A image (scaled by log2e)
__device__ __align__(16) __half g_wV[9216];       // Wv image

static __device__ __forceinline__ uint32_t smem_u32(const void* p) {
    uint32_t a;
    asm("{.reg .u64 t; cvta.to.shared.u64 t,%1; cvt.u32.u64 %0,t;}" : "=r"(a) : "l"(p));
    return a;
}
static __device__ __forceinline__ float ex2f(float x) {
    float y; asm("ex2.approx.f32 %0,%1;" : "=f"(y) : "f"(x)); return y;
}
#define LDSM4(r0,r1,r2,r3,a) asm volatile("ldmatrix.sync.aligned.m8n8.x4.shared.b16 {%0,%1,%2,%3},[%4];" \
    : "=r"(r0),"=r"(r1),"=r"(r2),"=r"(r3) : "r"(a))
#define LDSM4T(r0,r1,r2,r3,a) asm volatile("ldmatrix.sync.aligned.m8n8.x4.trans.shared.b16 {%0,%1,%2,%3},[%4];" \
    : "=r"(r0),"=r"(r1),"=r"(r2),"=r"(r3) : "r"(a))
#define LDSM2T(r0,r1,a) asm volatile("ldmatrix.sync.aligned.m8n8.x2.trans.shared.b16 {%0,%1},[%2];" \
    : "=r"(r0),"=r"(r1) : "r"(a))
#define MMA(d,a,b) asm volatile( \
    "mma.sync.aligned.m16n8k16.row.col.f32.f16.f16.f32 {%0,%1,%2,%3},{%4,%5,%6,%7},{%8,%9},{%0,%1,%2,%3};" \
    : "+f"((d)[0]),"+f"((d)[1]),"+f"((d)[2]),"+f"((d)[3]) \
    : "r"((a)[0]),"r"((a)[1]),"r"((a)[2]),"r"((a)[3]),"r"((b)[0]),"r"((b)[1]))
#define CPA16(dst, src)  asm volatile("cp.async.cg.shared.global [%0],[%1],16;" :: "r"(dst), "l"(src))
#define CPA_COMMIT()     asm volatile("cp.async.commit_group;" ::: "memory")
#define CPA_WAIT0()      asm volatile("cp.async.wait_group 0;" ::: "memory")

static __device__ __forceinline__ uint32_t h2pack(__half a, __half b) {
    return (uint32_t)__half_as_ushort(b) << 16 | (uint32_t)__half_as_ushort(a);
}
static __device__ __forceinline__ void split2(float x, float y, uint32_t& hi, uint32_t& lo) {
    __half hx = __float2half_rn(x), hy = __float2half_rn(y);
    __half lx = __float2half_rn(x - __half2float(hx));
    __half ly = __float2half_rn(y - __half2float(hy));
    hi = h2pack(hx, hy);
    lo = h2pack(lx, ly);
}
static __device__ __forceinline__ void dfrag_to_afrag(const float D[8][4], float s0, float s1,
                                                      uint32_t Ah[4][4], uint32_t Al[4][4]) {
    #pragma unroll
    for (int ks = 0; ks < 4; ++ks) {
        split2(D[2*ks][0]*s0,   D[2*ks][1]*s0,   Ah[ks][0], Al[ks][0]);
        split2(D[2*ks][2]*s1,   D[2*ks][3]*s1,   Ah[ks][1], Al[ks][1]);
        split2(D[2*ks+1][0]*s0, D[2*ks+1][1]*s0, Ah[ks][2], Al[ks][2]);
        split2(D[2*ks+1][2]*s1, D[2*ks+1][3]*s1, Ah[ks][3], Al[ks][3]);
    }
}
// hi-only with per-row scales (epilogue: ag-lo pass dropped)
static __device__ __forceinline__ void dfrag_to_afrag_hi_s(const float D[8][4], float s0, float s1,
                                                           uint32_t Ah[4][4]) {
    #pragma unroll
    for (int ks = 0; ks < 4; ++ks) {
        Ah[ks][0] = h2pack(__float2half_rn(D[2*ks][0]*s0),   __float2half_rn(D[2*ks][1]*s0));
        Ah[ks][1] = h2pack(__float2half_rn(D[2*ks][2]*s1),   __float2half_rn(D[2*ks][3]*s1));
        Ah[ks][2] = h2pack(__float2half_rn(D[2*ks+1][0]*s0), __float2half_rn(D[2*ks+1][1]*s0));
        Ah[ks][3] = h2pack(__float2half_rn(D[2*ks+1][2]*s1), __float2half_rn(D[2*ks+1][3]*s1));
    }
}

// ONE prep kernel, grid 288 x 256
__global__ void prep(const float* __restrict__ Wq, const float* __restrict__ bq,
                     const float* __restrict__ Wk, const float* __restrict__ nb,
                     const float* __restrict__ Wv) {
    int b = blockIdx.x;
    if (b < 256) {
        int idx = b * 256 + threadIdx.x;
        int row = idx >> 6, d = idx & 63;
        int t = row >> 6, j = row & 63;
        float v = nb[idx];
        __half h = __float2half_rn(v);
        __half l = __float2half_rn(v - __half2float(h));
        g_nb[t*9216 + j*STRD + d] = h;
        g_nb[t*9216 + 4608 + j*STRD + d] = l;
        if (d == 63) g_nb[t*9216 + j*STRD + 64] = __float2half_rn(1.0f);  // ones col
    } else if (b < 272) {
        int idx = (b - 256) * 256 + threadIdx.x;
        int j = idx >> 6, d = idx & 63;
        float s = 0.f;
        #pragma unroll 8
        for (int t = 0; t < 64; ++t) s += Wk[t*64 + j] * Wq[t*64 + d];
        s *= L2E;
        __half h = __float2half_rn(s);
        __half l = __float2half_rn(s - __half2float(h));
        g_wA[j*STRD + d] = h;
        g_wA[4608 + j*STRD + d] = l;
        if (b == 256 && threadIdx.x < 64) {
            int jj = threadIdx.x;
            float bb = 0.f;
            #pragma unroll 8
            for (int t = 0; t < 64; ++t) bb += Wk[t*64 + jj] * bq[t];
            g_bp[jj] = bb * L2E;
        }
    } else {
        int idx = (b - 272) * 256 + threadIdx.x;
        int o = idx >> 6, e = idx & 63;
        float v = Wv[idx];
        __half h = __float2half_rn(v);
        __half l = __float2half_rn(v - __half2float(h));
        g_wV[o*STRD + e] = h;
        g_wV[4608 + o*STRD + e] = l;
    }
}

__global__ void __launch_bounds__(NTHR, 4)
gat_kernel(const float* __restrict__ x, const float* __restrict__ bv,
           float* __restrict__ out, int N) {
    extern __shared__ char sm[];
    const uint32_t su = smem_u32(sm);
    const int tid = threadIdx.x, lane = tid & 31, wid = tid >> 5;
    const int g = lane >> 2, tg = lane & 3;
    const int m0 = wid * 16;
    const int n0 = blockIdx.x * BR;
    float* bias = (float*)(sm + BIAS_B);

    const int rN = ((lane >> 4) & 1) * 8 + (lane & 7);
    const int cN = ((lane >> 3) & 1) * 8;
    const int rT = ((lane >> 3) & 1) * 8 + (lane & 7);
    const int cT = ((lane >> 4) & 1) * 8;

    // ---- prologue: tile0 -> stage0, A image -> WH ----
    {
        const char* s0 = (const char*)g_nb;
        const char* sa = (const char*)g_wA;
        for (int i = tid; i < 1152; i += NTHR) {
            CPA16(su + i*16, s0 + i*16);
            CPA16(su + WH_B + i*16, sa + i*16);
        }
        CPA_COMMIT();
    }
    if (tid < 64) bias[tid] = g_bp[tid];

    // ---- x fragments straight from global ----
    uint32_t Xh[4][4], Xl[4][4];
    {
        int r0 = n0 + m0 + g, r1 = r0 + 8;
        #pragma unroll
        for (int q = 0; q < 8; ++q) {
            int c = 2*tg + 8*q;
            float2 v0 = make_float2(0.f, 0.f), v1 = make_float2(0.f, 0.f);
            if (r0 < N) v0 = *(const float2*)&x[(size_t)r0*DI + c];
            if (r1 < N) v1 = *(const float2*)&x[(size_t)r1*DI + c];
            int ks = q >> 1;
            if ((q & 1) == 0) {
                split2(v0.x, v0.y, Xh[ks][0], Xl[ks][0]);
                split2(v1.x, v1.y, Xh[ks][1], Xl[ks][1]);
            } else {
                split2(v0.x, v0.y, Xh[ks][2], Xl[ks][2]);
                split2(v1.x, v1.y, Xh[ks][3], Xl[ks][3]);
            }
        }
    }
    CPA_WAIT0();
    __syncthreads();

    // ---- GEMM0: p = (x @ A^T + bp) * log2e  (3-pass, precision-critical) ----
    float D[8][4];
    #pragma unroll
    for (int b = 0; b < 8; ++b) {
        D[b][0] = bias[8*b + 2*tg]; D[b][1] = bias[8*b + 2*tg + 1];
        D[b][2] = D[b][0];          D[b][3] = D[b][1];
    }
    #pragma unroll
    for (int ks = 0; ks < 4; ++ks)
        #pragma unroll
        for (int P = 0; P < 4; ++P) {
            uint32_t off = ((16*P + rN)*STRD + 16*ks + cN) * 2;
            uint32_t bh[4], bl[4];
            LDSM4(bh[0], bh[1], bh[2], bh[3], su + WH_B + off);
            LDSM4(bl[0], bl[1], bl[2], bl[3], su + WH_B + 9216 + off);
            MMA(D[2*P],   Xh[ks], bh);     MMA(D[2*P],   Xl[ks], bh);     MMA(D[2*P],   Xh[ks], bl);
            MMA(D[2*P+1], Xh[ks], bh+2);   MMA(D[2*P+1], Xl[ks], bh+2);   MMA(D[2*P+1], Xh[ks], bl+2);
        }
    uint32_t Ph[4][4], Pl[4][4];
    dfrag_to_afrag(D, 1.f, 1.f, Ph, Pl);

    // ---- flash loop (double-buffered nb stages) ----
    float ag[8][4];
    #pragma unroll
    for (int b = 0; b < 8; ++b)
        #pragma unroll
        for (int u = 0; u < 4; ++u) ag[b][u] = 0.f;
    float ags[4] = {0.f, 0.f, 0.f, 0.f};   // ones-column accumulator (row sums)
    float mr0 = -1e30f, mr1 = -1e30f;

    for (int t = 0; t < 16; ++t) {
        CPA_WAIT0();
        __syncthreads();
        {
            int nxt = t + 1;
            uint32_t dst = su + (nxt & 1) * STG_BYTES;
            if (nxt < 16) {
                const char* src = (const char*)g_nb + (size_t)nxt * STG_BYTES;
                for (int i = tid; i < 1152; i += NTHR) CPA16(dst + i*16, src + i*16);
            }
        }
        if (t == 0) {   // Wv image into weight region freed by GEMM0
            const char* sv = (const char*)g_wV;
            for (int i = tid; i < 1152; i += NTHR) CPA16(su + WH_B + i*16, sv + i*16);
        }
        CPA_COMMIT();
        const uint32_t sH = su + (t & 1) * STG_BYTES, sL = sH + 9216;

        // GEMM1: S = p @ nb^T (3-pass: logit precision drives softmax)
        float S[8][4];
        #pragma unroll
        for (int b = 0; b < 8; ++b)
            #pragma unroll
            for (int u = 0; u < 4; ++u) S[b][u] = 0.f;
        #pragma unroll
        for (int ks = 0; ks < 4; ++ks)
            #pragma unroll
            for (int P = 0; P < 4; ++P) {
                uint32_t off = ((16*P + rN)*STRD + 16*ks + cN) * 2;
                uint32_t bh[4], bl[4];
                LDSM4(bh[0], bh[1], bh[2], bh[3], sH + off);
                LDSM4(bl[0], bl[1], bl[2], bl[3], sL + off);
                MMA(S[2*P],   Ph[ks], bh);   MMA(S[2*P],   Pl[ks], bh);   MMA(S[2*P],   Ph[ks], bl);
                MMA(S[2*P+1], Ph[ks], bh+2); MMA(S[2*P+1], Pl[ks], bh+2); MMA(S[2*P+1], Ph[ks], bl+2);
            }

        // preload GEMM2 ks=0 B-frags (independent of softmax -> latency overlaps it)
        uint32_t pb[4][4], pbs[2];
        #pragma unroll
        for (int P = 0; P < 4; ++P)
            LDSM4T(pb[P][0], pb[P][1], pb[P][2], pb[P][3], sH + ((rT)*STRD + 16*P + cT) * 2);
        LDSM2T(pbs[0], pbs[1], sH + ((rT)*STRD + 64) * 2);

        // online softmax (log2 domain): f32 max + delta, fused cvt.f16x2 + ex2.f16x2 -> Th
        float mx0 = -1e30f, mx1 = -1e30f;
        #pragma unroll
        for (int b = 0; b < 8; ++b) {
            mx0 = fmaxf(mx0, fmaxf(S[b][0], S[b][1]));
            mx1 = fmaxf(mx1, fmaxf(S[b][2], S[b][3]));
        }
        mx0 = fmaxf(mx0, __shfl_xor_sync(0xFFFFFFFFu, mx0, 1));
        mx0 = fmaxf(mx0, __shfl_xor_sync(0xFFFFFFFFu, mx0, 2));
        mx1 = fmaxf(mx1, __shfl_xor_sync(0xFFFFFFFFu, mx1, 1));
        mx1 = fmaxf(mx1, __shfl_xor_sync(0xFFFFFFFFu, mx1, 2));
        float mn0 = fmaxf(mr0, mx0), mn1 = fmaxf(mr1, mx1);
        float sc0 = ex2f(mr0 - mn0), sc1 = ex2f(mr1 - mn1);
        mr0 = mn0; mr1 = mn1;

        uint32_t Th[4][4];
        #pragma unroll
        for (int b = 0; b < 8; ++b) {
            int ks = b >> 1, sl = (b & 1) * 2;
            uint32_t p0, p1;
            asm("cvt.rn.f16x2.f32 %0,%1,%2;" : "=r"(p0) : "f"(S[b][1]-mn0), "f"(S[b][0]-mn0));
            asm("cvt.rn.f16x2.f32 %0,%1,%2;" : "=r"(p1) : "f"(S[b][3]-mn1), "f"(S[b][2]-mn1));
            asm("ex2.approx.f16x2 %0,%1;" : "=r"(Th[ks][sl])     : "r"(p0));
            asm("ex2.approx.f16x2 %0,%1;" : "=r"(Th[ks][sl + 1]) : "r"(p1));
        }

        #pragma unroll
        for (int b = 0; b < 8; ++b) {
            ag[b][0] *= sc0; ag[b][1] *= sc0;
            ag[b][2] *= sc1; ag[b][3] *= sc1;
        }
        ags[0] *= sc0; ags[2] *= sc1;

        // GEMM2: ag += attn @ nb (single pass); ks=0 uses preloaded frags
        #pragma unroll
        for (int P = 0; P < 4; ++P) {
            MMA(ag[2*P],   Th[0], pb[P]);
            MMA(ag[2*P+1], Th[0], pb[P]+2);
        }
        MMA(ags, Th[0], pbs);
        #pragma unroll
        for (int ks = 1; ks < 4; ++ks) {
            #pragma unroll
            for (int P = 0; P < 4; ++P) {
                uint32_t off = ((16*ks + rT)*STRD + 16*P + cT) * 2;
                uint32_t bh[4];
                LDSM4T(bh[0], bh[1], bh[2], bh[3], sH + off);
                MMA(ag[2*P],   Th[ks], bh);
                MMA(ag[2*P+1], Th[ks], bh+2);
            }
            uint32_t b0, b1;
            LDSM2T(b0, b1, sH + ((16*ks + rT)*STRD + 64) * 2);
            uint32_t bs[2] = {b0, b1};
            MMA(ags, Th[ks], bs);
        }
    }

    // ---- row sums from ones column (lanes tg==0): broadcast within quad ----
    float lr0 = __shfl_sync(0xFFFFFFFFu, ags[0], lane & ~3);
    float lr1 = __shfl_sync(0xFFFFFFFFu, ags[2], lane & ~3);

    CPA_WAIT0();                 // Wv image landed long ago
    if (tid < 64) bias[tid] = bv[tid];
    __syncthreads();

    // ---- epilogue: normalize -> hi A-frags; GEMM3 (2-pass: ag-hi x Wv-hi + ag-hi x Wv-lo) ----
    float inv0 = 1.0f / lr0, inv1 = 1.0f / lr1;
    uint32_t Gh[4][4];
    dfrag_to_afrag_hi_s(ag, inv0, inv1, Gh);
    float O[8][4];
    #pragma unroll
    for (int b = 0; b < 8; ++b) {
        O[b][0] = bias[8*b + 2*tg]; O[b][1] = bias[8*b + 2*tg + 1];
        O[b][2] = O[b][0];          O[b][3] = O[b][1];
    }
    #pragma unroll
    for (int ks = 0; ks < 4; ++ks)
        #pragma unroll
        for (int P = 0; P < 4; ++P) {
            uint32_t off = ((16*P + rN)*STRD + 16*ks + cN) * 2;
            uint32_t bh[4], bl[4];
            LDSM4(bh[0], bh[1], bh[2], bh[3], su + WH_B + off);
            LDSM4(bl[0], bl[1], bl[2], bl[3], su + WH_B + 9216 + off);
            MMA(O[2*P],   Gh[ks], bh);   MMA(O[2*P],   Gh[ks], bl);
            MMA(O[2*P+1], Gh[ks], bh+2); MMA(O[2*P+1], Gh[ks], bl+2);
        }
    #pragma unroll
    for (int b = 0; b < 8; ++b) {
        int col = 8*b + 2*tg;
        int row0 = n0 + m0 + g;
        if (row0 < N) *(float2*)&out[(size_t)row0*DI + col] = make_float2(O[b][0], O[b][1]);
        int row1 = row0 + 8;
        if (row1 < N) *(float2*)&out[(size_t)row1*DI + col] = make_float2(O[b][2], O[b][3]);
    }
}

extern "C" void kernel_launch(void* const* d_in, const int* in_sizes, int n_in,
                              void* d_out, int out_size) {
    const float* x  = (const float*)d_in[0];
    const float* nb = (const float*)d_in[1];
    const float* Wq = (const float*)d_in[2];
    const float* bq = (const float*)d_in[3];
    const float* Wk = (const float*)d_in[4];
    // d_in[5] = bk drops out of softmax
    const float* Wv = (const float*)d_in[6];
    const float* bv = (const float*)d_in[7];
    float* out = (float*)d_out;
    const int N = in_sizes[0] / DI;
    cudaFuncSetAttribute(gat_kernel, cudaFuncAttributeMaxDynamicSharedMemorySize, SM_BYTES);
    prep<<<288, 256>>>(Wq, bq, Wk, nb, Wv);
    gat_kernel<<<(N + BR - 1) / BR, NTHR, SM_BYTES>>>(x, bv, out, N);
}

// round 16
// speedup vs baseline: 1.4248x; 1.2112x over previous
#include <cuda_runtime.h>
#include <cuda_fp16.h>
#include <cstdint>

#define DI 64
#define BR 64
#define NTHR 128
#define STRD 72                 // halves per smem row
#define STG_BYTES 9216          // one stage: hi 64x72 halves only
#define WH_B 18432              // weight region (A, then Wv): hi + lo images
#define BIAS_B 36864
#define SM_BYTES 37120
#define L2E 1.4426950408889634f

__device__ float g_bp[64];                        // log2e * (Wk^T bq)
__device__ __align__(16) __half g_nb[16 * 4608];  // per tile: hi image only; col64 = 1.0
__device__ __align__(16) __half g_wA[9216];       // A image hi+lo (scaled by log2e)
__device__ __align__(16) __half g_wV[9216];       // Wv image hi+lo

static __device__ __forceinline__ uint32_t smem_u32(const void* p) {
    uint32_t a;
    asm("{.reg .u64 t; cvta.to.shared.u64 t,%1; cvt.u32.u64 %0,t;}" : "=r"(a) : "l"(p));
    return a;
}
static __device__ __forceinline__ float ex2f(float x) {
    float y; asm("ex2.approx.f32 %0,%1;" : "=f"(y) : "f"(x)); return y;
}
#define LDSM4(r0,r1,r2,r3,a) asm volatile("ldmatrix.sync.aligned.m8n8.x4.shared.b16 {%0,%1,%2,%3},[%4];" \
    : "=r"(r0),"=r"(r1),"=r"(r2),"=r"(r3) : "r"(a))
#define LDSM4T(r0,r1,r2,r3,a) asm volatile("ldmatrix.sync.aligned.m8n8.x4.trans.shared.b16 {%0,%1,%2,%3},[%4];" \
    : "=r"(r0),"=r"(r1),"=r"(r2),"=r"(r3) : "r"(a))
#define LDSM2T(r0,r1,a) asm volatile("ldmatrix.sync.aligned.m8n8.x2.trans.shared.b16 {%0,%1},[%2];" \
    : "=r"(r0),"=r"(r1) : "r"(a))
#define MMA(d,a,b) asm volatile( \
    "mma.sync.aligned.m16n8k16.row.col.f32.f16.f16.f32 {%0,%1,%2,%3},{%4,%5,%6,%7},{%8,%9},{%0,%1,%2,%3};" \
    : "+f"((d)[0]),"+f"((d)[1]),"+f"((d)[2]),"+f"((d)[3]) \
    : "r"((a)[0]),"r"((a)[1]),"r"((a)[2]),"r"((a)[3]),"r"((b)[0]),"r"((b)[1]))
#define CPA16(dst, src)  asm volatile("cp.async.cg.shared.global [%0],[%1],16;" :: "r"(dst), "l"(src))
#define CPA_COMMIT()     asm volatile("cp.async.commit_group;" ::: "memory")
#define CPA_WAIT0()      asm volatile("cp.async.wait_group 0;" ::: "memory")

static __device__ __forceinline__ uint32_t h2pack(__half a, __half b) {
    return (uint32_t)__half_as_ushort(b) << 16 | (uint32_t)__half_as_ushort(a);
}
static __device__ __forceinline__ void split2(float x, float y, uint32_t& hi, uint32_t& lo) {
    __half hx = __float2half_rn(x), hy = __float2half_rn(y);
    __half lx = __float2half_rn(x - __half2float(hx));
    __half ly = __float2half_rn(y - __half2float(hy));
    hi = h2pack(hx, hy);
    lo = h2pack(lx, ly);
}
static __device__ __forceinline__ void dfrag_to_afrag(const float D[8][4], float s0, float s1,
                                                      uint32_t Ah[4][4], uint32_t Al[4][4]) {
    #pragma unroll
    for (int ks = 0; ks < 4; ++ks) {
        split2(D[2*ks][0]*s0,   D[2*ks][1]*s0,   Ah[ks][0], Al[ks][0]);
        split2(D[2*ks][2]*s1,   D[2*ks][3]*s1,   Ah[ks][1], Al[ks][1]);
        split2(D[2*ks+1][0]*s0, D[2*ks+1][1]*s0, Ah[ks][2], Al[ks][2]);
        split2(D[2*ks+1][2]*s1, D[2*ks+1][3]*s1, Ah[ks][3], Al[ks][3]);
    }
}
// hi-only with per-row scales (epilogue)
static __device__ __forceinline__ void dfrag_to_afrag_hi_s(const float D[8][4], float s0, float s1,
                                                           uint32_t Ah[4][4]) {
    #pragma unroll
    for (int ks = 0; ks < 4; ++ks) {
        Ah[ks][0] = h2pack(__float2half_rn(D[2*ks][0]*s0),   __float2half_rn(D[2*ks][1]*s0));
        Ah[ks][1] = h2pack(__float2half_rn(D[2*ks][2]*s1),   __float2half_rn(D[2*ks][3]*s1));
        Ah[ks][2] = h2pack(__float2half_rn(D[2*ks+1][0]*s0), __float2half_rn(D[2*ks+1][1]*s0));
        Ah[ks][3] = h2pack(__float2half_rn(D[2*ks+1][2]*s1), __float2half_rn(D[2*ks+1][3]*s1));
    }
}

// ONE prep kernel, grid 288 x 256
__global__ void prep(const float* __restrict__ Wq, const float* __restrict__ bq,
                     const float* __restrict__ Wk, const float* __restrict__ nb,
                     const float* __restrict__ Wv) {
    int b = blockIdx.x;
    if (b < 256) {
        int idx = b * 256 + threadIdx.x;
        int row = idx >> 6, d = idx & 63;
        int t = row >> 6, j = row & 63;
        g_nb[t*4608 + j*STRD + d] = __float2half_rn(nb[idx]);
        if (d == 63) g_nb[t*4608 + j*STRD + 64] = __float2half_rn(1.0f);  // ones col
    } else if (b < 272) {
        int idx = (b - 256) * 256 + threadIdx.x;
        int j = idx >> 6, d = idx & 63;
        float s = 0.f;
        #pragma unroll 8
        for (int t = 0; t < 64; ++t) s += Wk[t*64 + j] * Wq[t*64 + d];
        s *= L2E;
        __half h = __float2half_rn(s);
        __half l = __float2half_rn(s - __half2float(h));
        g_wA[j*STRD + d] = h;
        g_wA[4608 + j*STRD + d] = l;
        if (b == 256 && threadIdx.x < 64) {
            int jj = threadIdx.x;
            float bb = 0.f;
            #pragma unroll 8
            for (int t = 0; t < 64; ++t) bb += Wk[t*64 + jj] * bq[t];
            g_bp[jj] = bb * L2E;
        }
    } else {
        int idx = (b - 272) * 256 + threadIdx.x;
        int o = idx >> 6, e = idx & 63;
        float v = Wv[idx];
        __half h = __float2half_rn(v);
        __half l = __float2half_rn(v - __half2float(h));
        g_wV[o*STRD + e] = h;
        g_wV[4608 + o*STRD + e] = l;
    }
}

__global__ void __launch_bounds__(NTHR, 4)
gat_kernel(const float* __restrict__ x, const float* __restrict__ bv,
           float* __restrict__ out, int N) {
    extern __shared__ char sm[];
    const uint32_t su = smem_u32(sm);
    const int tid = threadIdx.x, lane = tid & 31, wid = tid >> 5;
    const int g = lane >> 2, tg = lane & 3;
    const int m0 = wid * 16;
    const int n0 = blockIdx.x * BR;
    float* bias = (float*)(sm + BIAS_B);

    const int rN = ((lane >> 4) & 1) * 8 + (lane & 7);
    const int cN = ((lane >> 3) & 1) * 8;
    const int rT = ((lane >> 3) & 1) * 8 + (lane & 7);
    const int cT = ((lane >> 4) & 1) * 8;

    // ---- prologue: tile0 -> stage0, A image -> WH ----
    {
        const char* s0 = (const char*)g_nb;
        const char* sa = (const char*)g_wA;
        for (int i = tid; i < 576; i += NTHR) CPA16(su + i*16, s0 + i*16);
        for (int i = tid; i < 1152; i += NTHR) CPA16(su + WH_B + i*16, sa + i*16);
        CPA_COMMIT();
    }
    if (tid < 64) bias[tid] = g_bp[tid];

    // ---- x fragments straight from global ----
    uint32_t Xh[4][4], Xl[4][4];
    {
        int r0 = n0 + m0 + g, r1 = r0 + 8;
        #pragma unroll
        for (int q = 0; q < 8; ++q) {
            int c = 2*tg + 8*q;
            float2 v0 = make_float2(0.f, 0.f), v1 = make_float2(0.f, 0.f);
            if (r0 < N) v0 = *(const float2*)&x[(size_t)r0*DI + c];
            if (r1 < N) v1 = *(const float2*)&x[(size_t)r1*DI + c];
            int ks = q >> 1;
            if ((q & 1) == 0) {
                split2(v0.x, v0.y, Xh[ks][0], Xl[ks][0]);
                split2(v1.x, v1.y, Xh[ks][1], Xl[ks][1]);
            } else {
                split2(v0.x, v0.y, Xh[ks][2], Xl[ks][2]);
                split2(v1.x, v1.y, Xh[ks][3], Xl[ks][3]);
            }
        }
    }
    CPA_WAIT0();
    __syncthreads();

    // ---- GEMM0: p = (x @ A^T + bp) * log2e  (3-pass, precision-critical) ----
    float D[8][4];
    #pragma unroll
    for (int b = 0; b < 8; ++b) {
        D[b][0] = bias[8*b + 2*tg]; D[b][1] = bias[8*b + 2*tg + 1];
        D[b][2] = D[b][0];          D[b][3] = D[b][1];
    }
    #pragma unroll
    for (int ks = 0; ks < 4; ++ks)
        #pragma unroll
        for (int P = 0; P < 4; ++P) {
            uint32_t off = ((16*P + rN)*STRD + 16*ks + cN) * 2;
            uint32_t bh[4], bl[4];
            LDSM4(bh[0], bh[1], bh[2], bh[3], su + WH_B + off);
            LDSM4(bl[0], bl[1], bl[2], bl[3], su + WH_B + 9216 + off);
            MMA(D[2*P],   Xh[ks], bh);     MMA(D[2*P],   Xl[ks], bh);     MMA(D[2*P],   Xh[ks], bl);
            MMA(D[2*P+1], Xh[ks], bh+2);   MMA(D[2*P+1], Xl[ks], bh+2);   MMA(D[2*P+1], Xh[ks], bl+2);
        }
    uint32_t Ph[4][4], Pl[4][4];
    dfrag_to_afrag(D, 1.f, 1.f, Ph, Pl);

    // ---- flash loop (double-buffered hi-only nb stages) ----
    float ag[8][4];
    #pragma unroll
    for (int b = 0; b < 8; ++b)
        #pragma unroll
        for (int u = 0; u < 4; ++u) ag[b][u] = 0.f;
    float ags[4] = {0.f, 0.f, 0.f, 0.f};   // ones-column accumulator (row sums)
    float mr0 = -1e30f, mr1 = -1e30f;

    for (int t = 0; t < 16; ++t) {
        CPA_WAIT0();
        __syncthreads();
        {
            int nxt = t + 1;
            if (nxt < 16) {
                uint32_t dst = su + (nxt & 1) * STG_BYTES;
                const char* src = (const char*)g_nb + (size_t)nxt * STG_BYTES;
                for (int i = tid; i < 576; i += NTHR) CPA16(dst + i*16, src + i*16);
            }
        }
        if (t == 0) {   // Wv image into weight region freed by GEMM0
            const char* sv = (const char*)g_wV;
            for (int i = tid; i < 1152; i += NTHR) CPA16(su + WH_B + i*16, sv + i*16);
        }
        CPA_COMMIT();
        const uint32_t sH = su + (t & 1) * STG_BYTES;

        // GEMM1: S = p @ nb^T (2-pass: Ph x nb-hi + Pl x nb-hi)
        float S[8][4];
        #pragma unroll
        for (int b = 0; b < 8; ++b)
            #pragma unroll
            for (int u = 0; u < 4; ++u) S[b][u] = 0.f;
        #pragma unroll
        for (int ks = 0; ks < 4; ++ks)
            #pragma unroll
            for (int P = 0; P < 4; ++P) {
                uint32_t off = ((16*P + rN)*STRD + 16*ks + cN) * 2;
                uint32_t bh[4];
                LDSM4(bh[0], bh[1], bh[2], bh[3], sH + off);
                MMA(S[2*P],   Ph[ks], bh);   MMA(S[2*P],   Pl[ks], bh);
                MMA(S[2*P+1], Ph[ks], bh+2); MMA(S[2*P+1], Pl[ks], bh+2);
            }

        // preload GEMM2 ks=0 B-frags (latency overlaps softmax)
        uint32_t pb[4][4], pbs[2];
        #pragma unroll
        for (int P = 0; P < 4; ++P)
            LDSM4T(pb[P][0], pb[P][1], pb[P][2], pb[P][3], sH + ((rT)*STRD + 16*P + cT) * 2);
        LDSM2T(pbs[0], pbs[1], sH + ((rT)*STRD + 64) * 2);

        // online softmax (log2 domain): f32 max + delta, fused cvt.f16x2 + ex2.f16x2 -> Th
        float mx0 = -1e30f, mx1 = -1e30f;
        #pragma unroll
        for (int b = 0; b < 8; ++b) {
            mx0 = fmaxf(mx0, fmaxf(S[b][0], S[b][1]));
            mx1 = fmaxf(mx1, fmaxf(S[b][2], S[b][3]));
        }
        mx0 = fmaxf(mx0, __shfl_xor_sync(0xFFFFFFFFu, mx0, 1));
        mx0 = fmaxf(mx0, __shfl_xor_sync(0xFFFFFFFFu, mx0, 2));
        mx1 = fmaxf(mx1, __shfl_xor_sync(0xFFFFFFFFu, mx1, 1));
        mx1 = fmaxf(mx1, __shfl_xor_sync(0xFFFFFFFFu, mx1, 2));
        float mn0 = fmaxf(mr0, mx0), mn1 = fmaxf(mr1, mx1);
        float sc0 = ex2f(mr0 - mn0), sc1 = ex2f(mr1 - mn1);
        mr0 = mn0; mr1 = mn1;

        uint32_t Th[4][4];
        #pragma unroll
        for (int b = 0; b < 8; ++b) {
            int ks = b >> 1, sl = (b & 1) * 2;
            uint32_t p0, p1;
            asm("cvt.rn.f16x2.f32 %0,%1,%2;" : "=r"(p0) : "f"(S[b][1]-mn0), "f"(S[b][0]-mn0));
            asm("cvt.rn.f16x2.f32 %0,%1,%2;" : "=r"(p1) : "f"(S[b][3]-mn1), "f"(S[b][2]-mn1));
            asm("ex2.approx.f16x2 %0,%1;" : "=r"(Th[ks][sl])     : "r"(p0));
            asm("ex2.approx.f16x2 %0,%1;" : "=r"(Th[ks][sl + 1]) : "r"(p1));
        }

        #pragma unroll
        for (int b = 0; b < 8; ++b) {
            ag[b][0] *= sc0; ag[b][1] *= sc0;
            ag[b][2] *= sc1; ag[b][3] *= sc1;
        }
        ags[0] *= sc0; ags[2] *= sc1;

        // GEMM2: ag += attn @ nb (single pass); ks=0 uses preloaded frags
        #pragma unroll
        for (int P = 0; P < 4; ++P) {
            MMA(ag[2*P],   Th[0], pb[P]);
            MMA(ag[2*P+1], Th[0], pb[P]+2);
        }
        MMA(ags, Th[0], pbs);
        #pragma unroll
        for (int ks = 1; ks < 4; ++ks) {
            #pragma unroll
            for (int P = 0; P < 4; ++P) {
                uint32_t off = ((16*ks + rT)*STRD + 16*P + cT) * 2;
                uint32_t bh[4];
                LDSM4T(bh[0], bh[1], bh[2], bh[3], sH + off);
                MMA(ag[2*P],   Th[ks], bh);
                MMA(ag[2*P+1], Th[ks], bh+2);
            }
            uint32_t b0, b1;
            LDSM2T(b0, b1, sH + ((16*ks + rT)*STRD + 64) * 2);
            uint32_t bs[2] = {b0, b1};
            MMA(ags, Th[ks], bs);
        }
    }

    // ---- row sums from ones column (lanes tg==0): broadcast within quad ----
    float lr0 = __shfl_sync(0xFFFFFFFFu, ags[0], lane & ~3);
    float lr1 = __shfl_sync(0xFFFFFFFFu, ags[2], lane & ~3);

    CPA_WAIT0();                 // Wv image landed long ago
    if (tid < 64) bias[tid] = bv[tid];
    __syncthreads();

    // ---- epilogue: normalize -> hi A-frags; GEMM3 (2-pass); store ----
    float inv0 = 1.0f / lr0, inv1 = 1.0f / lr1;
    uint32_t Gh[4][4];
    dfrag_to_afrag_hi_s(ag, inv0, inv1, Gh);
    float O[8][4];
    #pragma unroll
    for (int b = 0; b < 8; ++b) {
        O[b][0] = bias[8*b + 2*tg]; O[b][1] = bias[8*b + 2*tg + 1];
        O[b][2] = O[b][0];          O[b][3] = O[b][1];
    }
    #pragma unroll
    for (int ks = 0; ks < 4; ++ks)
        #pragma unroll
        for (int P = 0; P < 4; ++P) {
            uint32_t off = ((16*P + rN)*STRD + 16*ks + cN) * 2;
            uint32_t bh[4], bl[4];
            LDSM4(bh[0], bh[1], bh[2], bh[3], su + WH_B + off);
            LDSM4(bl[0], bl[1], bl[2], bl[3], su + WH_B + 9216 + off);
            MMA(O[2*P],   Gh[ks], bh);   MMA(O[2*P],   Gh[ks], bl);
            MMA(O[2*P+1], Gh[ks], bh+2); MMA(O[2*P+1], Gh[ks], bl+2);
        }
    #pragma unroll
    for (int b = 0; b < 8; ++b) {
        int col = 8*b + 2*tg;
        int row0 = n0 + m0 + g;
        if (row0 < N) *(float2*)&out[(size_t)row0*DI + col] = make_float2(O[b][0], O[b][1]);
        int row1 = row0 + 8;
        if (row1 < N) *(float2*)&out[(size_t)row1*DI + col] = make_float2(O[b][2], O[b][3]);
    }
}

extern "C" void kernel_launch(void* const* d_in, const int* in_sizes, int n_in,
                              void* d_out, int out_size) {
    const float* x  = (const float*)d_in[0];
    const float* nb = (const float*)d_in[1];
    const float* Wq = (const float*)d_in[2];
    const float* bq = (const float*)d_in[3];
    const float* Wk = (const float*)d_in[4];
    // d_in[5] = bk drops out of softmax
    const float* Wv = (const float*)d_in[6];
    const float* bv = (const float*)d_in[7];
    float* out = (float*)d_out;
    const int N = in_sizes[0] / DI;
    cudaFuncSetAttribute(gat_kernel, cudaFuncAttributeMaxDynamicSharedMemorySize, SM_BYTES);
    prep<<<288, 256>>>(Wq, bq, Wk, nb, Wv);
    gat_kernel<<<(N + BR - 1) / BR, NTHR, SM_BYTES>>>(x, bv, out, N);
}